// round 1
// baseline (speedup 1.0000x reference)
#include <cuda_runtime.h>
#include <math.h>

// ---------------- problem constants (fixed by setup_inputs) ----------------
#define B_   4
#define S_   1024
#define HD   2048
#define NH   16
#define NKV  4
#define DH   128
#define T_   (B_*S_)        // 4096 tokens
#define KVD  (NKV*DH)       // 512

// ---------------- scratch (device globals; no allocation allowed) ----------
__device__ float g_xn  [(size_t)T_*HD];
__device__ float g_q   [(size_t)T_*HD];
__device__ float g_k   [(size_t)T_*KVD];
__device__ float g_v   [(size_t)T_*KVD];
__device__ float g_sc  [(size_t)B_*NH*S_*S_];   // 64 * 1024 * 1024 = 256 MB
__device__ float g_ctx [(size_t)T_*HD];
__device__ float g_ao  [(size_t)T_*HD];
__device__ float g_h   [(size_t)T_*HD];
__device__ float g_gate[(size_t)T_*HD];
__device__ float g_up  [(size_t)T_*HD];

// ---------------- RMSNorm: one block per token row ------------------------
__global__ void rmsnorm_k(const float* __restrict__ x, const float* __restrict__ g,
                          float* __restrict__ o) {
    __shared__ float sh[256];
    int row = blockIdx.x;
    const float* xr = x + (long long)row * HD;
    float s = 0.f;
    for (int c = threadIdx.x; c < HD; c += 256) { float v = xr[c]; s += v * v; }
    sh[threadIdx.x] = s; __syncthreads();
    for (int st = 128; st > 0; st >>= 1) {
        if (threadIdx.x < st) sh[threadIdx.x] += sh[threadIdx.x + st];
        __syncthreads();
    }
    float inv = 1.0f / sqrtf(sh[0] / (float)HD + 1e-8f);
    float* orow = o + (long long)row * HD;
    for (int c = threadIdx.x; c < HD; c += 256) orow[c] = xr[c] * inv * g[c];
}

// ---------------- RoPE (interleaved pairs), in place -----------------------
__global__ void rope_k(float* __restrict__ x, int cols) {
    long long idx = (long long)blockIdx.x * blockDim.x + threadIdx.x;
    int halfc = cols >> 1;
    long long total = (long long)T_ * halfc;
    if (idx >= total) return;
    int pc = (int)(idx % halfc);
    int t  = (int)(idx / halfc);
    int s  = t % S_;
    int c0 = pc * 2;
    int d  = c0 & (DH - 1);                 // even index within head
    float inv = powf(10000.0f, -(float)d / (float)DH);
    float ang = (float)s * inv;
    float sn, cs; sincosf(ang, &sn, &cs);
    float* p = x + (long long)t * cols + c0;
    float x0 = p[0], x1 = p[1];
    p[0] = cs * x0 - sn * x1;
    p[1] = cs * x1 + sn * x0;
}

// ---------------- tiled SGEMM 64x64x16, 4x4 per thread ---------------------
// C = scale*(A @ op(B)) + bias[n] + resid[m,n]
// NT=true:  B is row-major [N,K] (ldb = row stride), computes A @ B^T
// NT=false: B is row-major [K,N]
// batched via blockIdx.z: offA = bb*sAb + hh*sAh ; offB = bb*sBb + (hh/grpB)*sBh
//                         offC = bb*sCb + hh*sCh   with bb=bz/HPB, hh=bz%HPB
template<bool NT>
__global__ void gemm_k(const float* __restrict__ A, const float* __restrict__ B,
                       float* __restrict__ C, const float* __restrict__ bias,
                       const float* __restrict__ resid,
                       int M, int N, int K, int lda, int ldb, int ldc, int ldr,
                       int HPB, int grpB,
                       long long sAb, long long sAh,
                       long long sBb, long long sBh,
                       long long sCb, long long sCh,
                       float scale) {
    __shared__ float As[16][68];
    __shared__ float Bs[16][68];

    int bz = blockIdx.z;
    int bb = bz / HPB, hh = bz % HPB;
    A += bb * sAb + (long long)hh * sAh;
    B += bb * sBb + (long long)(hh / grpB) * sBh;
    C += bb * sCb + (long long)hh * sCh;

    int m0 = blockIdx.y * 64, n0 = blockIdx.x * 64;
    int tid = threadIdx.x;
    int tx = tid & 15, ty = tid >> 4;

    // loader indices
    int arow = tid >> 2;            // 0..63
    int akv  = (tid & 3) * 4;       // 0,4,8,12
    int bk   = tid >> 4;            // 0..15
    int bnv  = (tid & 15) * 4;      // 0..60

    float acc[4][4] = {};

    for (int k0 = 0; k0 < K; k0 += 16) {
        float4 a4 = *reinterpret_cast<const float4*>(
            &A[(long long)(m0 + arow) * lda + k0 + akv]);
        As[akv + 0][arow] = a4.x; As[akv + 1][arow] = a4.y;
        As[akv + 2][arow] = a4.z; As[akv + 3][arow] = a4.w;

        if (NT) {
            float4 b4 = *reinterpret_cast<const float4*>(
                &B[(long long)(n0 + arow) * ldb + k0 + akv]);
            Bs[akv + 0][arow] = b4.x; Bs[akv + 1][arow] = b4.y;
            Bs[akv + 2][arow] = b4.z; Bs[akv + 3][arow] = b4.w;
        } else {
            float4 b4 = *reinterpret_cast<const float4*>(
                &B[(long long)(k0 + bk) * ldb + n0 + bnv]);
            Bs[bk][bnv + 0] = b4.x; Bs[bk][bnv + 1] = b4.y;
            Bs[bk][bnv + 2] = b4.z; Bs[bk][bnv + 3] = b4.w;
        }
        __syncthreads();

        #pragma unroll
        for (int kk = 0; kk < 16; kk++) {
            float ra[4], rb[4];
            #pragma unroll
            for (int i = 0; i < 4; i++) ra[i] = As[kk][ty * 4 + i];
            #pragma unroll
            for (int j = 0; j < 4; j++) rb[j] = Bs[kk][tx * 4 + j];
            #pragma unroll
            for (int i = 0; i < 4; i++)
                #pragma unroll
                for (int j = 0; j < 4; j++)
                    acc[i][j] += ra[i] * rb[j];
        }
        __syncthreads();
    }

    #pragma unroll
    for (int i = 0; i < 4; i++) {
        int m = m0 + ty * 4 + i;
        #pragma unroll
        for (int j = 0; j < 4; j++) {
            int n = n0 + tx * 4 + j;
            float v = acc[i][j] * scale;
            if (bias)  v += bias[n];
            if (resid) v += resid[(long long)m * ldr + n];
            C[(long long)m * ldc + n] = v;
        }
    }
}

// ---------------- masked softmax: one block per (b,h,s) row ----------------
__global__ void softmax_k(float* __restrict__ sc, const float* __restrict__ mask) {
    __shared__ float sh[256];
    long long row = blockIdx.x;                     // over B*NH*S
    int s = (int)(row % S_);
    int b = (int)(row / ((long long)NH * S_));
    float* p = sc + row * S_;
    float ms = mask[b * S_ + s];

    float vals[4];
    float mx = -INFINITY;
    #pragma unroll
    for (int i = 0; i < 4; i++) {
        int t = threadIdx.x + i * 256;
        float v = p[t];
        if (ms * mask[b * S_ + t] == 0.0f) v = -1e30f;
        vals[i] = v;
        mx = fmaxf(mx, v);
    }
    sh[threadIdx.x] = mx; __syncthreads();
    for (int st = 128; st > 0; st >>= 1) {
        if (threadIdx.x < st) sh[threadIdx.x] = fmaxf(sh[threadIdx.x], sh[threadIdx.x + st]);
        __syncthreads();
    }
    mx = sh[0]; __syncthreads();

    float sum = 0.f;
    #pragma unroll
    for (int i = 0; i < 4; i++) { vals[i] = expf(vals[i] - mx); sum += vals[i]; }
    sh[threadIdx.x] = sum; __syncthreads();
    for (int st = 128; st > 0; st >>= 1) {
        if (threadIdx.x < st) sh[threadIdx.x] += sh[threadIdx.x + st];
        __syncthreads();
    }
    float inv = 1.0f / sh[0];
    #pragma unroll
    for (int i = 0; i < 4; i++) p[threadIdx.x + i * 256] = vals[i] * inv;
}

// ---------------- SiLU(gate) * up, in place into gate ----------------------
__global__ void silu_k(float* __restrict__ gate, const float* __restrict__ up) {
    long long i = (long long)blockIdx.x * blockDim.x + threadIdx.x;
    if (i >= (long long)T_ * HD) return;
    float gv = gate[i];
    float sg = 1.0f / (1.0f + expf(-gv));
    gate[i] = gv * sg * up[i];
}

// ---------------- host launcher --------------------------------------------
static void launch_gemm(bool nt, const float* A, const float* B, float* C,
                        const float* bias, const float* resid,
                        int M, int N, int K, int lda, int ldb, int ldc, int ldr,
                        int batch, int HPB, int grpB,
                        long long sAb, long long sAh,
                        long long sBb, long long sBh,
                        long long sCb, long long sCh,
                        float scale) {
    dim3 grid(N / 64, M / 64, batch), block(256);
    if (nt)
        gemm_k<true><<<grid, block>>>(A, B, C, bias, resid, M, N, K, lda, ldb, ldc,
                                      ldr, HPB, grpB, sAb, sAh, sBb, sBh, sCb, sCh, scale);
    else
        gemm_k<false><<<grid, block>>>(A, B, C, bias, resid, M, N, K, lda, ldb, ldc,
                                       ldr, HPB, grpB, sAb, sAh, sBb, sBh, sCb, sCh, scale);
}

extern "C" void kernel_launch(void* const* d_in, const int* in_sizes, int n_in,
                              void* d_out, int out_size) {
    const float* enc    = (const float*)d_in[0];
    const float* mask   = (const float*)d_in[1];
    // d_in[2], d_in[3]: num_heads / num_kv_heads (compile-time constants here)
    const float* gin    = (const float*)d_in[4];
    const float* gffn   = (const float*)d_in[5];
    const float* w_q    = (const float*)d_in[6];
    const float* b_q    = (const float*)d_in[7];
    const float* w_k    = (const float*)d_in[8];
    const float* b_k    = (const float*)d_in[9];
    const float* w_v    = (const float*)d_in[10];
    const float* b_v    = (const float*)d_in[11];
    const float* w_o    = (const float*)d_in[12];
    const float* b_o    = (const float*)d_in[13];
    const float* w_gate = (const float*)d_in[14];
    const float* b_gate = (const float*)d_in[15];
    const float* w_up   = (const float*)d_in[16];
    const float* b_up   = (const float*)d_in[17];
    const float* w_down = (const float*)d_in[18];
    const float* b_down = (const float*)d_in[19];
    float* out = (float*)d_out;

    float *xn, *q, *k, *v, *sc, *ctx, *ao, *h, *gate, *up;
    cudaGetSymbolAddress((void**)&xn,   g_xn);
    cudaGetSymbolAddress((void**)&q,    g_q);
    cudaGetSymbolAddress((void**)&k,    g_k);
    cudaGetSymbolAddress((void**)&v,    g_v);
    cudaGetSymbolAddress((void**)&sc,   g_sc);
    cudaGetSymbolAddress((void**)&ctx,  g_ctx);
    cudaGetSymbolAddress((void**)&ao,   g_ao);
    cudaGetSymbolAddress((void**)&h,    g_h);
    cudaGetSymbolAddress((void**)&gate, g_gate);
    cudaGetSymbolAddress((void**)&up,   g_up);

    const float scale = 1.0f / sqrtf((float)DH);

    // 1) x = RMSNorm(enc, g_in)
    rmsnorm_k<<<T_, 256>>>(enc, gin, xn);

    // 2) Q/K/V projections (NN)
    launch_gemm(false, xn, w_q, q, b_q, nullptr, T_, HD,  HD, HD, HD,  HD, 0,
                1, 1, 1, 0, 0, 0, 0, 0, 0, 1.0f);
    launch_gemm(false, xn, w_k, k, b_k, nullptr, T_, KVD, HD, HD, KVD, KVD, 0,
                1, 1, 1, 0, 0, 0, 0, 0, 0, 1.0f);
    launch_gemm(false, xn, w_v, v, b_v, nullptr, T_, KVD, HD, HD, KVD, KVD, 0,
                1, 1, 1, 0, 0, 0, 0, 0, 0, 1.0f);

    // 3) RoPE on q (16 heads) and k (4 heads)
    {
        long long pq = (long long)T_ * HD / 2;
        long long pk = (long long)T_ * KVD / 2;
        rope_k<<<(unsigned)((pq + 255) / 256), 256>>>(q, HD);
        rope_k<<<(unsigned)((pk + 255) / 256), 256>>>(k, KVD);
    }

    // 4) scores[b,h] = (Q_bh @ K_bh^T) / sqrt(D)   (batched NT, 64 batches)
    launch_gemm(true, q, k, sc, nullptr, nullptr,
                S_, S_, DH, HD, KVD, S_, 0,
                B_ * NH, NH, NKV,
                (long long)S_ * HD, DH,
                (long long)S_ * KVD, DH,
                (long long)NH * S_ * S_, (long long)S_ * S_,
                scale);

    // 5) masked softmax over rows
    softmax_k<<<B_ * NH * S_, 256>>>(sc, mask);

    // 6) ctx[b,h] = attn @ V_bh  -> packed [B,S,H*D]  (batched NN)
    launch_gemm(false, sc, v, ctx, nullptr, nullptr,
                S_, DH, S_, S_, KVD, HD, 0,
                B_ * NH, NH, NKV,
                (long long)NH * S_ * S_, (long long)S_ * S_,
                (long long)S_ * KVD, DH,
                (long long)S_ * HD, DH,
                1.0f);

    // 7) attn_out = enc + ctx @ w_o + b_o
    launch_gemm(false, ctx, w_o, ao, b_o, enc, T_, HD, HD, HD, HD, HD, HD,
                1, 1, 1, 0, 0, 0, 0, 0, 0, 1.0f);

    // 8) h = RMSNorm(attn_out, g_ffn)
    rmsnorm_k<<<T_, 256>>>(ao, gffn, h);

    // 9) gate / up projections
    launch_gemm(false, h, w_gate, gate, b_gate, nullptr, T_, HD, HD, HD, HD, HD, 0,
                1, 1, 1, 0, 0, 0, 0, 0, 0, 1.0f);
    launch_gemm(false, h, w_up, up, b_up, nullptr, T_, HD, HD, HD, HD, HD, 0,
                1, 1, 1, 0, 0, 0, 0, 0, 0, 1.0f);

    // 10) gate = SiLU(gate) * up
    {
        long long n = (long long)T_ * HD;
        silu_k<<<(unsigned)((n + 255) / 256), 256>>>(gate, up);
    }

    // 11) out = attn_out + gate' @ w_down + b_down
    launch_gemm(false, gate, w_down, out, b_down, ao, T_, HD, HD, HD, HD, HD, HD,
                1, 1, 1, 0, 0, 0, 0, 0, 0, 1.0f);
}

// round 2
// speedup vs baseline: 2.0008x; 2.0008x over previous
#include <cuda_runtime.h>
#include <math.h>

// ---------------- problem constants (fixed by setup_inputs) ----------------
#define B_   4
#define S_   1024
#define HD   2048
#define NH   16
#define NKV  4
#define DH   128
#define T_   (B_*S_)        // 4096 tokens
#define KVD  (NKV*DH)       // 512

// ---------------- scratch (device globals; no allocation allowed) ----------
__device__ float g_xn  [(size_t)T_*HD];
__device__ float g_q   [(size_t)T_*HD];
__device__ float g_k   [(size_t)T_*KVD];
__device__ float g_v   [(size_t)T_*KVD];
__device__ float g_sc  [(size_t)B_*NH*S_*S_];   // 256 MB
__device__ float g_ctx [(size_t)T_*HD];
__device__ float g_ao  [(size_t)T_*HD];
__device__ float g_h   [(size_t)T_*HD];
__device__ float g_gate[(size_t)T_*HD];
__device__ float g_up  [(size_t)T_*HD];

// ---------------- helpers ---------------------------------------------------
__device__ __forceinline__ float f2tf32(float f) {
    unsigned u;
    asm("cvt.rna.tf32.f32 %0, %1;" : "=r"(u) : "f"(f));
    return __uint_as_float(u);
}

__device__ __forceinline__ void mma_tf32(float c[4],
                                         unsigned a0, unsigned a1, unsigned a2, unsigned a3,
                                         unsigned b0, unsigned b1) {
    asm volatile(
        "mma.sync.aligned.m16n8k8.row.col.f32.tf32.tf32.f32 "
        "{%0,%1,%2,%3},{%4,%5,%6,%7},{%8,%9},{%0,%1,%2,%3};\n"
        : "+f"(c[0]), "+f"(c[1]), "+f"(c[2]), "+f"(c[3])
        : "r"(a0), "r"(a1), "r"(a2), "r"(a3), "r"(b0), "r"(b1));
}

// ---------------- RMSNorm: one block per token row ------------------------
__global__ void rmsnorm_k(const float* __restrict__ x, const float* __restrict__ g,
                          float* __restrict__ o) {
    __shared__ float sh[256];
    int row = blockIdx.x;
    const float* xr = x + (long long)row * HD;
    float s = 0.f;
    for (int c = threadIdx.x; c < HD; c += 256) { float v = xr[c]; s += v * v; }
    sh[threadIdx.x] = s; __syncthreads();
    for (int st = 128; st > 0; st >>= 1) {
        if (threadIdx.x < st) sh[threadIdx.x] += sh[threadIdx.x + st];
        __syncthreads();
    }
    float inv = 1.0f / sqrtf(sh[0] / (float)HD + 1e-8f);
    float* orow = o + (long long)row * HD;
    for (int c = threadIdx.x; c < HD; c += 256) orow[c] = xr[c] * inv * g[c];
}

// ---------------- RoPE (interleaved pairs), in place -----------------------
__global__ void rope_k(float* __restrict__ x, int cols) {
    long long idx = (long long)blockIdx.x * blockDim.x + threadIdx.x;
    int halfc = cols >> 1;
    long long total = (long long)T_ * halfc;
    if (idx >= total) return;
    int pc = (int)(idx % halfc);
    int t  = (int)(idx / halfc);
    int s  = t % S_;
    int c0 = pc * 2;
    int d  = c0 & (DH - 1);
    float inv = powf(10000.0f, -(float)d / (float)DH);
    float ang = (float)s * inv;
    float sn, cs; sincosf(ang, &sn, &cs);
    float* p = x + (long long)t * cols + c0;
    float x0 = p[0], x1 = p[1];
    p[0] = cs * x0 - sn * x1;
    p[1] = cs * x1 + sn * x0;
}

// ---------------- TF32 tensor-core GEMM -------------------------------------
// C = scale*(A @ op(B)) + bias[n] + resid[m,n]
// NT=true:  B row-major [N,K]  -> computes A @ B^T
// NT=false: B row-major [K,N]
// Block tile 128x128, BK=16, 256 threads (8 warps, 2Mx4N), warp tile 64x32.
// Batched via blockIdx.z (bb = bz/HPB, hh = bz%HPB; B uses hh/grpB for GQA).
template<bool NT>
__global__ __launch_bounds__(256, 1)
void mma_gemm_k(const float* __restrict__ A, const float* __restrict__ Bm,
                float* __restrict__ C, const float* __restrict__ bias,
                const float* __restrict__ resid,
                int M, int N, int K, int lda, int ldb, int ldc, int ldr,
                int HPB, int grpB,
                long long sAb, long long sAh,
                long long sBb, long long sBh,
                long long sCb, long long sCh,
                float scale) {
    // As: [buf][m(128)][k(16) pad 20]
    __shared__ __align__(16) float As[2 * 128 * 20];
    // Bs: NT -> [buf][n(128)][k pad 20] ; NN -> [buf][k(16)][n(128) pad 136]
    __shared__ __align__(16) float Bs[NT ? (2 * 128 * 20) : (2 * 16 * 136)];

    const int tid  = threadIdx.x;
    const int lane = tid & 31;
    const int warp = tid >> 5;
    const int warpM = warp >> 2;   // 0..1
    const int warpN = warp & 3;    // 0..3

    int bz = blockIdx.z;
    int bb = bz / HPB, hh = bz % HPB;
    A  += bb * sAb + (long long)hh * sAh;
    Bm += bb * sBb + (long long)(hh / grpB) * sBh;
    C  += bb * sCb + (long long)hh * sCh;

    const int m0 = blockIdx.y * 128, n0 = blockIdx.x * 128;

    float4 ra[2], rb[2];

    auto ldg = [&](int k0) {
        #pragma unroll
        for (int i = 0; i < 2; i++) {
            int idx = tid + 256 * i;
            ra[i] = *reinterpret_cast<const float4*>(
                &A[(long long)(m0 + (idx >> 2)) * lda + k0 + (idx & 3) * 4]);
            if (NT) {
                rb[i] = *reinterpret_cast<const float4*>(
                    &Bm[(long long)(n0 + (idx >> 2)) * ldb + k0 + (idx & 3) * 4]);
            } else {
                rb[i] = *reinterpret_cast<const float4*>(
                    &Bm[(long long)(k0 + (idx >> 5)) * ldb + n0 + (idx & 31) * 4]);
            }
        }
    };

    auto sts = [&](int buf) {
        #pragma unroll
        for (int i = 0; i < 2; i++) {
            int idx = tid + 256 * i;
            float4 a = ra[i];
            a.x = f2tf32(a.x); a.y = f2tf32(a.y); a.z = f2tf32(a.z); a.w = f2tf32(a.w);
            *reinterpret_cast<float4*>(&As[buf * 2560 + (idx >> 2) * 20 + (idx & 3) * 4]) = a;
            float4 b = rb[i];
            b.x = f2tf32(b.x); b.y = f2tf32(b.y); b.z = f2tf32(b.z); b.w = f2tf32(b.w);
            if (NT) {
                *reinterpret_cast<float4*>(&Bs[buf * 2560 + (idx >> 2) * 20 + (idx & 3) * 4]) = b;
            } else {
                *reinterpret_cast<float4*>(&Bs[buf * 2176 + (idx >> 5) * 136 + (idx & 31) * 4]) = b;
            }
        }
    };

    float c[4][4][4];
    #pragma unroll
    for (int i = 0; i < 4; i++)
        #pragma unroll
        for (int j = 0; j < 4; j++)
            #pragma unroll
            for (int q = 0; q < 4; q++) c[i][j][q] = 0.f;

    const int ktiles = K >> 4;
    ldg(0);
    sts(0);
    __syncthreads();

    for (int kt = 0; kt < ktiles; kt++) {
        const int buf = kt & 1;
        if (kt + 1 < ktiles) ldg((kt + 1) << 4);

        #pragma unroll
        for (int k8 = 0; k8 < 2; k8++) {
            const int kb = k8 * 8 + (lane & 3);
            unsigned af[4][4], bf[4][2];
            #pragma unroll
            for (int i = 0; i < 4; i++) {
                int mr = warpM * 64 + i * 16 + (lane >> 2);
                const float* pa = &As[buf * 2560 + mr * 20];
                af[i][0] = __float_as_uint(pa[kb]);
                af[i][1] = __float_as_uint(pa[8 * 20 + kb]);
                af[i][2] = __float_as_uint(pa[kb + 4]);
                af[i][3] = __float_as_uint(pa[8 * 20 + kb + 4]);
            }
            #pragma unroll
            for (int j = 0; j < 4; j++) {
                int nr = warpN * 32 + j * 8 + (lane >> 2);
                if (NT) {
                    const float* pb = &Bs[buf * 2560 + nr * 20];
                    bf[j][0] = __float_as_uint(pb[kb]);
                    bf[j][1] = __float_as_uint(pb[kb + 4]);
                } else {
                    bf[j][0] = __float_as_uint(Bs[buf * 2176 + kb * 136 + nr]);
                    bf[j][1] = __float_as_uint(Bs[buf * 2176 + (kb + 4) * 136 + nr]);
                }
            }
            #pragma unroll
            for (int i = 0; i < 4; i++)
                #pragma unroll
                for (int j = 0; j < 4; j++)
                    mma_tf32(c[i][j], af[i][0], af[i][1], af[i][2], af[i][3],
                             bf[j][0], bf[j][1]);
        }

        if (kt + 1 < ktiles) {
            sts((kt + 1) & 1);
            __syncthreads();
        }
    }

    // epilogue
    #pragma unroll
    for (int i = 0; i < 4; i++) {
        int r = m0 + warpM * 64 + i * 16 + (lane >> 2);
        #pragma unroll
        for (int j = 0; j < 4; j++) {
            int cn = n0 + warpN * 32 + j * 8 + (lane & 3) * 2;
            float b0 = 0.f, b1 = 0.f;
            if (bias) { b0 = bias[cn]; b1 = bias[cn + 1]; }
            // rows r and r+8
            float v0 = c[i][j][0] * scale + b0;
            float v1 = c[i][j][1] * scale + b1;
            float v2 = c[i][j][2] * scale + b0;
            float v3 = c[i][j][3] * scale + b1;
            if (resid) {
                const float* rr0 = &resid[(long long)r * ldr + cn];
                const float* rr1 = &resid[(long long)(r + 8) * ldr + cn];
                v0 += rr0[0]; v1 += rr0[1];
                v2 += rr1[0]; v3 += rr1[1];
            }
            float2 o0 = make_float2(v0, v1);
            float2 o1 = make_float2(v2, v3);
            *reinterpret_cast<float2*>(&C[(long long)r * ldc + cn]) = o0;
            *reinterpret_cast<float2*>(&C[(long long)(r + 8) * ldc + cn]) = o1;
        }
    }
}

// ---------------- masked softmax: one block per (b,h,s) row ----------------
__global__ void softmax_k(float* __restrict__ sc, const float* __restrict__ mask) {
    __shared__ float sh[256];
    long long row = blockIdx.x;
    int s = (int)(row % S_);
    int b = (int)(row / ((long long)NH * S_));
    float* p = sc + row * S_;
    float ms = mask[b * S_ + s];

    float vals[4];
    float mx = -INFINITY;
    #pragma unroll
    for (int i = 0; i < 4; i++) {
        int t = threadIdx.x + i * 256;
        float v = p[t];
        if (ms * mask[b * S_ + t] == 0.0f) v = -1e30f;
        vals[i] = v;
        mx = fmaxf(mx, v);
    }
    sh[threadIdx.x] = mx; __syncthreads();
    for (int st = 128; st > 0; st >>= 1) {
        if (threadIdx.x < st) sh[threadIdx.x] = fmaxf(sh[threadIdx.x], sh[threadIdx.x + st]);
        __syncthreads();
    }
    mx = sh[0]; __syncthreads();

    float sum = 0.f;
    #pragma unroll
    for (int i = 0; i < 4; i++) { vals[i] = expf(vals[i] - mx); sum += vals[i]; }
    sh[threadIdx.x] = sum; __syncthreads();
    for (int st = 128; st > 0; st >>= 1) {
        if (threadIdx.x < st) sh[threadIdx.x] += sh[threadIdx.x + st];
        __syncthreads();
    }
    float inv = 1.0f / sh[0];
    #pragma unroll
    for (int i = 0; i < 4; i++) p[threadIdx.x + i * 256] = vals[i] * inv;
}

// ---------------- SiLU(gate) * up, in place into gate ----------------------
__global__ void silu_k(float* __restrict__ gate, const float* __restrict__ up) {
    long long i = (long long)blockIdx.x * blockDim.x + threadIdx.x;
    if (i >= (long long)T_ * HD) return;
    float gv = gate[i];
    float sg = 1.0f / (1.0f + expf(-gv));
    gate[i] = gv * sg * up[i];
}

// ---------------- host launcher --------------------------------------------
static void launch_gemm(bool nt, const float* A, const float* B, float* C,
                        const float* bias, const float* resid,
                        int M, int N, int K, int lda, int ldb, int ldc, int ldr,
                        int batch, int HPB, int grpB,
                        long long sAb, long long sAh,
                        long long sBb, long long sBh,
                        long long sCb, long long sCh,
                        float scale) {
    dim3 grid(N / 128, M / 128, batch), block(256);
    if (nt)
        mma_gemm_k<true><<<grid, block>>>(A, B, C, bias, resid, M, N, K, lda, ldb, ldc,
                                          ldr, HPB, grpB, sAb, sAh, sBb, sBh, sCb, sCh, scale);
    else
        mma_gemm_k<false><<<grid, block>>>(A, B, C, bias, resid, M, N, K, lda, ldb, ldc,
                                           ldr, HPB, grpB, sAb, sAh, sBb, sBh, sCb, sCh, scale);
}

extern "C" void kernel_launch(void* const* d_in, const int* in_sizes, int n_in,
                              void* d_out, int out_size) {
    const float* enc    = (const float*)d_in[0];
    const float* mask   = (const float*)d_in[1];
    const float* gin    = (const float*)d_in[4];
    const float* gffn   = (const float*)d_in[5];
    const float* w_q    = (const float*)d_in[6];
    const float* b_q    = (const float*)d_in[7];
    const float* w_k    = (const float*)d_in[8];
    const float* b_k    = (const float*)d_in[9];
    const float* w_v    = (const float*)d_in[10];
    const float* b_v    = (const float*)d_in[11];
    const float* w_o    = (const float*)d_in[12];
    const float* b_o    = (const float*)d_in[13];
    const float* w_gate = (const float*)d_in[14];
    const float* b_gate = (const float*)d_in[15];
    const float* w_up   = (const float*)d_in[16];
    const float* b_up   = (const float*)d_in[17];
    const float* w_down = (const float*)d_in[18];
    const float* b_down = (const float*)d_in[19];
    float* out = (float*)d_out;

    float *xn, *q, *k, *v, *sc, *ctx, *ao, *h, *gate, *up;
    cudaGetSymbolAddress((void**)&xn,   g_xn);
    cudaGetSymbolAddress((void**)&q,    g_q);
    cudaGetSymbolAddress((void**)&k,    g_k);
    cudaGetSymbolAddress((void**)&v,    g_v);
    cudaGetSymbolAddress((void**)&sc,   g_sc);
    cudaGetSymbolAddress((void**)&ctx,  g_ctx);
    cudaGetSymbolAddress((void**)&ao,   g_ao);
    cudaGetSymbolAddress((void**)&h,    g_h);
    cudaGetSymbolAddress((void**)&gate, g_gate);
    cudaGetSymbolAddress((void**)&up,   g_up);

    const float scale = 1.0f / sqrtf((float)DH);

    // 1) x = RMSNorm(enc, g_in)
    rmsnorm_k<<<T_, 256>>>(enc, gin, xn);

    // 2) Q/K/V projections (NN)
    launch_gemm(false, xn, w_q, q, b_q, nullptr, T_, HD,  HD, HD, HD,  HD, 0,
                1, 1, 1, 0, 0, 0, 0, 0, 0, 1.0f);
    launch_gemm(false, xn, w_k, k, b_k, nullptr, T_, KVD, HD, HD, KVD, KVD, 0,
                1, 1, 1, 0, 0, 0, 0, 0, 0, 1.0f);
    launch_gemm(false, xn, w_v, v, b_v, nullptr, T_, KVD, HD, HD, KVD, KVD, 0,
                1, 1, 1, 0, 0, 0, 0, 0, 0, 1.0f);

    // 3) RoPE on q (16 heads) and k (4 heads)
    {
        long long pq = (long long)T_ * HD / 2;
        long long pk = (long long)T_ * KVD / 2;
        rope_k<<<(unsigned)((pq + 255) / 256), 256>>>(q, HD);
        rope_k<<<(unsigned)((pk + 255) / 256), 256>>>(k, KVD);
    }

    // 4) scores[b,h] = (Q_bh @ K_bh^T) / sqrt(D)   (batched NT, 64 batches)
    launch_gemm(true, q, k, sc, nullptr, nullptr,
                S_, S_, DH, HD, KVD, S_, 0,
                B_ * NH, NH, NKV,
                (long long)S_ * HD, DH,
                (long long)S_ * KVD, DH,
                (long long)NH * S_ * S_, (long long)S_ * S_,
                scale);

    // 5) masked softmax over rows
    softmax_k<<<B_ * NH * S_, 256>>>(sc, mask);

    // 6) ctx[b,h] = attn @ V_bh -> packed [B,S,H*D]  (batched NN)
    launch_gemm(false, sc, v, ctx, nullptr, nullptr,
                S_, DH, S_, S_, KVD, HD, 0,
                B_ * NH, NH, NKV,
                (long long)NH * S_ * S_, (long long)S_ * S_,
                (long long)S_ * KVD, DH,
                (long long)S_ * HD, DH,
                1.0f);

    // 7) attn_out = enc + ctx @ w_o + b_o
    launch_gemm(false, ctx, w_o, ao, b_o, enc, T_, HD, HD, HD, HD, HD, HD,
                1, 1, 1, 0, 0, 0, 0, 0, 0, 1.0f);

    // 8) h = RMSNorm(attn_out, g_ffn)
    rmsnorm_k<<<T_, 256>>>(ao, gffn, h);

    // 9) gate / up projections
    launch_gemm(false, h, w_gate, gate, b_gate, nullptr, T_, HD, HD, HD, HD, HD, 0,
                1, 1, 1, 0, 0, 0, 0, 0, 0, 1.0f);
    launch_gemm(false, h, w_up, up, b_up, nullptr, T_, HD, HD, HD, HD, HD, 0,
                1, 1, 1, 0, 0, 0, 0, 0, 0, 1.0f);

    // 10) gate = SiLU(gate) * up
    {
        long long n = (long long)T_ * HD;
        silu_k<<<(unsigned)((n + 255) / 256), 256>>>(gate, up);
    }

    // 11) out = attn_out + gate' @ w_down + b_down
    launch_gemm(false, gate, w_down, out, b_down, ao, T_, HD, HD, HD, HD, HD, HD,
                1, 1, 1, 0, 0, 0, 0, 0, 0, 1.0f);
}

// round 4
// speedup vs baseline: 5.6061x; 2.8019x over previous
#include <cuda_runtime.h>
#include <cuda_fp16.h>
#include <cstdint>
#include <math.h>

// ---------------- problem constants ----------------
#define B_   4
#define S_   1024
#define HD   2048
#define NH   16
#define NKV  4
#define DH   128
#define T_   (B_*S_)        // 4096
#define KVD  (NKV*DH)       // 512

// ---------------- scratch (device globals) ----------
// fp32
__device__ float g_q   [(size_t)T_*HD];
__device__ float g_k   [(size_t)T_*KVD];
__device__ float g_sc  [(size_t)B_*NH*S_*S_];
__device__ float g_ao  [(size_t)T_*HD];
__device__ float g_gate[(size_t)T_*HD];
__device__ float g_up  [(size_t)T_*HD];
// fp16
__device__ __half g_wqh[(size_t)HD*HD];
__device__ __half g_wkh[(size_t)HD*KVD];
__device__ __half g_wvh[(size_t)HD*KVD];
__device__ __half g_woh[(size_t)HD*HD];
__device__ __half g_wgh[(size_t)HD*HD];
__device__ __half g_wuh[(size_t)HD*HD];
__device__ __half g_wdh[(size_t)HD*HD];
__device__ __half g_xnh[(size_t)T_*HD];
__device__ __half g_qh [(size_t)T_*HD];
__device__ __half g_kh [(size_t)T_*KVD];
__device__ __half g_vh [(size_t)T_*KVD];
__device__ __half g_ath[(size_t)B_*NH*S_*S_];
__device__ __half g_cxh[(size_t)T_*HD];
__device__ __half g_hh [(size_t)T_*HD];
__device__ __half g_guh[(size_t)T_*HD];

// ---------------- ptx helpers -----------------------
__device__ __forceinline__ void cpa16(unsigned int dst, const void* src) {
    asm volatile("cp.async.cg.shared.global [%0], [%1], 16;\n" :: "r"(dst), "l"(src));
}
__device__ __forceinline__ void cpa_commit() {
    asm volatile("cp.async.commit_group;\n");
}
template<int N>
__device__ __forceinline__ void cpa_wait() {
    asm volatile("cp.async.wait_group %0;\n" :: "n"(N));
}
__device__ __forceinline__ void ldsm4(unsigned &r0, unsigned &r1, unsigned &r2, unsigned &r3,
                                      unsigned int addr) {
    asm volatile("ldmatrix.sync.aligned.m8n8.x4.shared.b16 {%0,%1,%2,%3}, [%4];\n"
                 : "=r"(r0), "=r"(r1), "=r"(r2), "=r"(r3) : "r"(addr));
}
__device__ __forceinline__ void ldsm4t(unsigned &r0, unsigned &r1, unsigned &r2, unsigned &r3,
                                       unsigned int addr) {
    asm volatile("ldmatrix.sync.aligned.m8n8.x4.trans.shared.b16 {%0,%1,%2,%3}, [%4];\n"
                 : "=r"(r0), "=r"(r1), "=r"(r2), "=r"(r3) : "r"(addr));
}
__device__ __forceinline__ void mma16816(float c[4], const unsigned a[4], const unsigned b[2]) {
    asm volatile(
        "mma.sync.aligned.m16n8k16.row.col.f32.f16.f16.f32 "
        "{%0,%1,%2,%3},{%4,%5,%6,%7},{%8,%9},{%0,%1,%2,%3};\n"
        : "+f"(c[0]), "+f"(c[1]), "+f"(c[2]), "+f"(c[3])
        : "r"(a[0]), "r"(a[1]), "r"(a[2]), "r"(a[3]), "r"(b[0]), "r"(b[1]));
}

// ---------------- fp16 tensor-core GEMM ----------------------------------
// C = scale*(A @ op(B)) + bias[n] + resid[m,n]
// A fp16 row-major [M,K]. NT: B fp16 [N,K]; NN: B fp16 [K,N].
// Output fp32 (Cf) or fp16 (Ch) per OUTH.
// Block 128x128x32, 3-stage cp.async, 8 warps (2x4), warp tile 64x32.
template<bool NT, bool OUTH>
__global__ __launch_bounds__(256, 2)
void hgemm_k(const __half* __restrict__ A, const __half* __restrict__ B,
             float* __restrict__ Cf, __half* __restrict__ Ch,
             const float* __restrict__ bias, const float* __restrict__ resid,
             int M, int N, int K, int lda, int ldb, int ldc, int ldr,
             int HPB, int grpB,
             long long sAb, long long sAh,
             long long sBb, long long sBh,
             long long sCb, long long sCh,
             float scale) {
    constexpr int ASTG = 128 * 40;                    // halves per A stage (80B rows)
    constexpr int BSTG = NT ? 128 * 40 : 32 * 136;    // halves per B stage
    extern __shared__ __half sm[];
    __half* sA = sm;
    __half* sB = sm + 3 * ASTG;

    const int tid = threadIdx.x, lane = tid & 31, warp = tid >> 5;
    const int warpM = warp >> 2, warpN = warp & 3;

    const int bz = blockIdx.z;
    const int bb = bz / HPB, hh = bz % HPB;
    A += bb * sAb + (long long)hh * sAh;
    B += bb * sBb + (long long)(hh / grpB) * sBh;
    const long long coff = bb * sCb + (long long)hh * sCh;
    if (OUTH) Ch += coff; else Cf += coff;

    const int m0 = blockIdx.y * 128, n0 = blockIdx.x * 128;

    const unsigned int suA = (unsigned int)__cvta_generic_to_shared(sA);
    const unsigned int suB = (unsigned int)__cvta_generic_to_shared(sB);

    const int arow = tid >> 2, akc = tid & 3;          // A/B-NT loader coords
    const int bkr = tid >> 4, bnc = tid & 15;          // B-NN loader coords

    auto load_stage = [&](int kt, int buf) {
        const int k0 = kt << 5;
        #pragma unroll
        for (int i = 0; i < 2; i++) {
            int row = arow + i * 64;
            cpa16(suA + (unsigned int)(buf * ASTG + row * 40 + akc * 8) * 2,
                  A + (long long)(m0 + row) * lda + k0 + akc * 8);
        }
        if (NT) {
            #pragma unroll
            for (int i = 0; i < 2; i++) {
                int row = arow + i * 64;
                cpa16(suB + (unsigned int)(buf * BSTG + row * 40 + akc * 8) * 2,
                      B + (long long)(n0 + row) * ldb + k0 + akc * 8);
            }
        } else {
            #pragma unroll
            for (int i = 0; i < 2; i++) {
                int kr = bkr + i * 16;
                cpa16(suB + (unsigned int)(buf * BSTG + kr * 136 + bnc * 8) * 2,
                      B + (long long)(k0 + kr) * ldb + n0 + bnc * 8);
            }
        }
    };

    float acc[4][4][4];
    #pragma unroll
    for (int i = 0; i < 4; i++)
        #pragma unroll
        for (int j = 0; j < 4; j++)
            #pragma unroll
            for (int q = 0; q < 4; q++) acc[i][j][q] = 0.f;

    const int ktiles = K >> 5;
    load_stage(0, 0); cpa_commit();
    if (ktiles > 1) load_stage(1, 1);
    cpa_commit();

    int buf = 0;
    for (int kt = 0; kt < ktiles; kt++) {
        cpa_wait<1>();
        __syncthreads();
        {
            int pf = kt + 2;
            if (pf < ktiles) {
                int pbuf = buf + 2; if (pbuf >= 3) pbuf -= 3;
                load_stage(pf, pbuf);
            }
            cpa_commit();
        }

        #pragma unroll
        for (int kk = 0; kk < 2; kk++) {
            unsigned af[4][4], bf[4][2];
            const int ar = warpM * 64 + (lane & 15);
            const int ac = kk * 16 + (lane >> 4) * 8;
            #pragma unroll
            for (int i = 0; i < 4; i++)
                ldsm4(af[i][0], af[i][1], af[i][2], af[i][3],
                      suA + (unsigned int)(buf * ASTG + (ar + i * 16) * 40 + ac) * 2);

            if (NT) {
                const int br = (lane >> 4) * 8 + (lane & 7);
                const int bc = kk * 16 + ((lane >> 3) & 1) * 8;
                #pragma unroll
                for (int jj = 0; jj < 2; jj++) {
                    const int nb = warpN * 32 + jj * 16;
                    ldsm4(bf[jj*2][0], bf[jj*2][1], bf[jj*2+1][0], bf[jj*2+1][1],
                          suB + (unsigned int)(buf * BSTG + (nb + br) * 40 + bc) * 2);
                }
            } else {
                const int kr = kk * 16 + (lane & 15);
                const int ncl = (lane >> 4) * 8;
                #pragma unroll
                for (int jj = 0; jj < 2; jj++) {
                    const int nb = warpN * 32 + jj * 16;
                    ldsm4t(bf[jj*2][0], bf[jj*2][1], bf[jj*2+1][0], bf[jj*2+1][1],
                           suB + (unsigned int)(buf * BSTG + kr * 136 + nb + ncl) * 2);
                }
            }
            #pragma unroll
            for (int i = 0; i < 4; i++)
                #pragma unroll
                for (int j = 0; j < 4; j++)
                    mma16816(acc[i][j], af[i], bf[j]);
        }
        buf++; if (buf >= 3) buf -= 3;
    }

    // epilogue
    #pragma unroll
    for (int i = 0; i < 4; i++) {
        const int r = m0 + warpM * 64 + i * 16 + (lane >> 2);
        #pragma unroll
        for (int j = 0; j < 4; j++) {
            const int cn = n0 + warpN * 32 + j * 8 + (lane & 3) * 2;
            float b0 = 0.f, b1 = 0.f;
            if (bias) { b0 = bias[cn]; b1 = bias[cn + 1]; }
            float v0 = acc[i][j][0] * scale + b0;
            float v1 = acc[i][j][1] * scale + b1;
            float v2 = acc[i][j][2] * scale + b0;
            float v3 = acc[i][j][3] * scale + b1;
            if (resid) {
                const float* rr0 = &resid[(long long)r * ldr + cn];
                const float* rr1 = &resid[(long long)(r + 8) * ldr + cn];
                v0 += rr0[0]; v1 += rr0[1]; v2 += rr1[0]; v3 += rr1[1];
            }
            if (OUTH) {
                *reinterpret_cast<__half2*>(&Ch[(long long)r * ldc + cn]) =
                    __floats2half2_rn(v0, v1);
                *reinterpret_cast<__half2*>(&Ch[(long long)(r + 8) * ldc + cn]) =
                    __floats2half2_rn(v2, v3);
            } else {
                *reinterpret_cast<float2*>(&Cf[(long long)r * ldc + cn]) = make_float2(v0, v1);
                *reinterpret_cast<float2*>(&Cf[(long long)(r + 8) * ldc + cn]) = make_float2(v2, v3);
            }
        }
    }
}

// ---------------- elementwise kernels ---------------------------------------
__global__ void f2h_k(const float* __restrict__ a, __half* __restrict__ o, int n) {
    int i = (blockIdx.x * blockDim.x + threadIdx.x) * 4;
    if (i >= n) return;
    float4 v = *reinterpret_cast<const float4*>(&a[i]);
    *reinterpret_cast<__half2*>(&o[i])     = __floats2half2_rn(v.x, v.y);
    *reinterpret_cast<__half2*>(&o[i + 2]) = __floats2half2_rn(v.z, v.w);
}

__global__ void rmsnorm_h(const float* __restrict__ x, const float* __restrict__ g,
                          __half* __restrict__ o) {
    __shared__ float sh[256];
    int row = blockIdx.x;
    const float* xr = x + (long long)row * HD;
    float s = 0.f;
    for (int c = threadIdx.x; c < HD; c += 256) { float v = xr[c]; s += v * v; }
    sh[threadIdx.x] = s; __syncthreads();
    for (int st = 128; st > 0; st >>= 1) {
        if (threadIdx.x < st) sh[threadIdx.x] += sh[threadIdx.x + st];
        __syncthreads();
    }
    float inv = 1.0f / sqrtf(sh[0] / (float)HD + 1e-8f);
    __half* orow = o + (long long)row * HD;
    for (int c = threadIdx.x; c < HD; c += 256)
        orow[c] = __float2half(xr[c] * inv * g[c]);
}

__global__ void rope_h(const float* __restrict__ x, __half* __restrict__ o, int cols) {
    long long idx = (long long)blockIdx.x * blockDim.x + threadIdx.x;
    int halfc = cols >> 1;
    long long total = (long long)T_ * halfc;
    if (idx >= total) return;
    int pc = (int)(idx % halfc);
    int t  = (int)(idx / halfc);
    int s  = t % S_;
    int c0 = pc * 2;
    int d  = c0 & (DH - 1);
    float inv = powf(10000.0f, -(float)d / (float)DH);
    float ang = (float)s * inv;
    float sn, cs; sincosf(ang, &sn, &cs);
    const float* p = x + (long long)t * cols + c0;
    float x0 = p[0], x1 = p[1];
    *reinterpret_cast<__half2*>(&o[(long long)t * cols + c0]) =
        __floats2half2_rn(cs * x0 - sn * x1, cs * x1 + sn * x0);
}

__global__ void softmax_k(const float* __restrict__ sc, const float* __restrict__ mask,
                          __half* __restrict__ attn) {
    __shared__ float sh[256];
    long long row = blockIdx.x;
    int s = (int)(row % S_);
    int b = (int)(row / ((long long)NH * S_));
    const float* p = sc + row * S_;
    float ms = mask[b * S_ + s];

    float vals[4];
    float mx = -INFINITY;
    #pragma unroll
    for (int i = 0; i < 4; i++) {
        int t = threadIdx.x + i * 256;
        float v = p[t];
        if (ms * mask[b * S_ + t] == 0.0f) v = -1e30f;
        vals[i] = v;
        mx = fmaxf(mx, v);
    }
    sh[threadIdx.x] = mx; __syncthreads();
    for (int st = 128; st > 0; st >>= 1) {
        if (threadIdx.x < st) sh[threadIdx.x] = fmaxf(sh[threadIdx.x], sh[threadIdx.x + st]);
        __syncthreads();
    }
    mx = sh[0]; __syncthreads();

    float sum = 0.f;
    #pragma unroll
    for (int i = 0; i < 4; i++) { vals[i] = expf(vals[i] - mx); sum += vals[i]; }
    sh[threadIdx.x] = sum; __syncthreads();
    for (int st = 128; st > 0; st >>= 1) {
        if (threadIdx.x < st) sh[threadIdx.x] += sh[threadIdx.x + st];
        __syncthreads();
    }
    float inv = 1.0f / sh[0];
    __half* ar = attn + row * S_;
    #pragma unroll
    for (int i = 0; i < 4; i++)
        ar[threadIdx.x + i * 256] = __float2half(vals[i] * inv);
}

__global__ void silu_k(const float* __restrict__ gate, const float* __restrict__ up,
                       __half* __restrict__ o) {
    long long i = (long long)blockIdx.x * blockDim.x + threadIdx.x;
    if (i >= (long long)T_ * HD) return;
    float gv = gate[i];
    float sg = 1.0f / (1.0f + expf(-gv));
    o[i] = __float2half(gv * sg * up[i]);
}

// ---------------- host side --------------------------------------------------
static const int SMEM_NT = 3 * (128 * 40 + 128 * 40) * 2;   // 61440
static const int SMEM_NN = 3 * (128 * 40 + 32 * 136) * 2;   // 56832

static void launch_hgemm(bool nt, const __half* A, const __half* B,
                         float* Cf, __half* Ch,
                         const float* bias, const float* resid,
                         int M, int N, int K, int lda, int ldb, int ldc, int ldr,
                         int batch, int HPB, int grpB,
                         long long sAb, long long sAh,
                         long long sBb, long long sBh,
                         long long sCb, long long sCh,
                         float scale) {
    dim3 grid(N / 128, M / 128, batch), block(256);
    if (nt) {
        cudaFuncSetAttribute(hgemm_k<true, false>,
                             cudaFuncAttributeMaxDynamicSharedMemorySize, SMEM_NT);
        hgemm_k<true, false><<<grid, block, SMEM_NT>>>(
            A, B, Cf, Ch, bias, resid, M, N, K, lda, ldb, ldc, ldr,
            HPB, grpB, sAb, sAh, sBb, sBh, sCb, sCh, scale);
    } else if (Ch) {
        cudaFuncSetAttribute(hgemm_k<false, true>,
                             cudaFuncAttributeMaxDynamicSharedMemorySize, SMEM_NN);
        hgemm_k<false, true><<<grid, block, SMEM_NN>>>(
            A, B, Cf, Ch, bias, resid, M, N, K, lda, ldb, ldc, ldr,
            HPB, grpB, sAb, sAh, sBb, sBh, sCb, sCh, scale);
    } else {
        cudaFuncSetAttribute(hgemm_k<false, false>,
                             cudaFuncAttributeMaxDynamicSharedMemorySize, SMEM_NN);
        hgemm_k<false, false><<<grid, block, SMEM_NN>>>(
            A, B, Cf, Ch, bias, resid, M, N, K, lda, ldb, ldc, ldr,
            HPB, grpB, sAb, sAh, sBb, sBh, sCb, sCh, scale);
    }
}

extern "C" void kernel_launch(void* const* d_in, const int* in_sizes, int n_in,
                              void* d_out, int out_size) {
    const float* enc    = (const float*)d_in[0];
    const float* mask   = (const float*)d_in[1];
    const float* gin    = (const float*)d_in[4];
    const float* gffn   = (const float*)d_in[5];
    const float* w_q    = (const float*)d_in[6];
    const float* b_q    = (const float*)d_in[7];
    const float* w_k    = (const float*)d_in[8];
    const float* b_k    = (const float*)d_in[9];
    const float* w_v    = (const float*)d_in[10];
    const float* b_v    = (const float*)d_in[11];
    const float* w_o    = (const float*)d_in[12];
    const float* b_o    = (const float*)d_in[13];
    const float* w_gate = (const float*)d_in[14];
    const float* b_gate = (const float*)d_in[15];
    const float* w_up   = (const float*)d_in[16];
    const float* b_up   = (const float*)d_in[17];
    const float* w_down = (const float*)d_in[18];
    const float* b_down = (const float*)d_in[19];
    float* out = (float*)d_out;

    float *q, *k, *sc, *ao, *gate, *up;
    __half *wqh, *wkh, *wvh, *woh, *wgh, *wuh, *wdh;
    __half *xnh, *qh, *kh, *vh, *ath, *cxh, *hh, *guh;
    cudaGetSymbolAddress((void**)&q,   g_q);
    cudaGetSymbolAddress((void**)&k,   g_k);
    cudaGetSymbolAddress((void**)&sc,  g_sc);
    cudaGetSymbolAddress((void**)&ao,  g_ao);
    cudaGetSymbolAddress((void**)&gate,g_gate);
    cudaGetSymbolAddress((void**)&up,  g_up);
    cudaGetSymbolAddress((void**)&wqh, g_wqh);
    cudaGetSymbolAddress((void**)&wkh, g_wkh);
    cudaGetSymbolAddress((void**)&wvh, g_wvh);
    cudaGetSymbolAddress((void**)&woh, g_woh);
    cudaGetSymbolAddress((void**)&wgh, g_wgh);
    cudaGetSymbolAddress((void**)&wuh, g_wuh);
    cudaGetSymbolAddress((void**)&wdh, g_wdh);
    cudaGetSymbolAddress((void**)&xnh, g_xnh);
    cudaGetSymbolAddress((void**)&qh,  g_qh);
    cudaGetSymbolAddress((void**)&kh,  g_kh);
    cudaGetSymbolAddress((void**)&vh,  g_vh);
    cudaGetSymbolAddress((void**)&ath, g_ath);
    cudaGetSymbolAddress((void**)&cxh, g_cxh);
    cudaGetSymbolAddress((void**)&hh,  g_hh);
    cudaGetSymbolAddress((void**)&guh, g_guh);

    const float scale = 1.0f / sqrtf((float)DH);

    // 0) convert weights to fp16
    {
        int n1 = HD * HD, n2 = HD * KVD;
        f2h_k<<<n1 / 1024, 256>>>(w_q,    wqh, n1);
        f2h_k<<<n2 / 1024, 256>>>(w_k,    wkh, n2);
        f2h_k<<<n2 / 1024, 256>>>(w_v,    wvh, n2);
        f2h_k<<<n1 / 1024, 256>>>(w_o,    woh, n1);
        f2h_k<<<n1 / 1024, 256>>>(w_gate, wgh, n1);
        f2h_k<<<n1 / 1024, 256>>>(w_up,   wuh, n1);
        f2h_k<<<n1 / 1024, 256>>>(w_down, wdh, n1);
    }

    // 1) x = RMSNorm(enc) -> fp16
    rmsnorm_h<<<T_, 256>>>(enc, gin, xnh);

    // 2) Q/K/V projections
    launch_hgemm(false, xnh, wqh, q, nullptr, b_q, nullptr,
                 T_, HD, HD, HD, HD, HD, 0, 1, 1, 1, 0,0,0,0,0,0, 1.0f);
    launch_hgemm(false, xnh, wkh, k, nullptr, b_k, nullptr,
                 T_, KVD, HD, HD, KVD, KVD, 0, 1, 1, 1, 0,0,0,0,0,0, 1.0f);
    launch_hgemm(false, xnh, wvh, nullptr, vh, b_v, nullptr,
                 T_, KVD, HD, HD, KVD, KVD, 0, 1, 1, 1, 0,0,0,0,0,0, 1.0f);

    // 3) RoPE -> fp16
    {
        long long pq = (long long)T_ * HD / 2;
        long long pk = (long long)T_ * KVD / 2;
        rope_h<<<(unsigned)((pq + 255) / 256), 256>>>(q, qh, HD);
        rope_h<<<(unsigned)((pk + 255) / 256), 256>>>(k, kh, KVD);
    }

    // 4) scores = (Q @ K^T)/sqrt(D)  (batched NT, 64 batches)
    launch_hgemm(true, qh, kh, sc, nullptr, nullptr, nullptr,
                 S_, S_, DH, HD, KVD, S_, 0,
                 B_ * NH, NH, NKV,
                 (long long)S_ * HD, DH,
                 (long long)S_ * KVD, DH,
                 (long long)NH * S_ * S_, (long long)S_ * S_,
                 scale);

    // 5) masked softmax -> fp16 attn
    softmax_k<<<B_ * NH * S_, 256>>>(sc, mask, ath);

    // 6) ctx = attn @ V -> fp16 packed [B,S,H*D]
    launch_hgemm(false, ath, vh, nullptr, cxh, nullptr, nullptr,
                 S_, DH, S_, S_, KVD, HD, 0,
                 B_ * NH, NH, NKV,
                 (long long)NH * S_ * S_, (long long)S_ * S_,
                 (long long)S_ * KVD, DH,
                 (long long)S_ * HD, DH,
                 1.0f);

    // 7) attn_out = enc + ctx @ w_o + b_o   (fp32)
    launch_hgemm(false, cxh, woh, ao, nullptr, b_o, enc,
                 T_, HD, HD, HD, HD, HD, HD, 1, 1, 1, 0,0,0,0,0,0, 1.0f);

    // 8) h = RMSNorm(attn_out) -> fp16
    rmsnorm_h<<<T_, 256>>>(ao, gffn, hh);

    // 9) gate / up (fp32 outs)
    launch_hgemm(false, hh, wgh, gate, nullptr, b_gate, nullptr,
                 T_, HD, HD, HD, HD, HD, 0, 1, 1, 1, 0,0,0,0,0,0, 1.0f);
    launch_hgemm(false, hh, wuh, up, nullptr, b_up, nullptr,
                 T_, HD, HD, HD, HD, HD, 0, 1, 1, 1, 0,0,0,0,0,0, 1.0f);

    // 10) gu = SiLU(gate)*up -> fp16
    {
        long long n = (long long)T_ * HD;
        silu_k<<<(unsigned)((n + 255) / 256), 256>>>(gate, up, guh);
    }

    // 11) out = attn_out + gu @ w_down + b_down
    launch_hgemm(false, guh, wdh, out, nullptr, b_down, ao,
                 T_, HD, HD, HD, HD, HD, HD, 1, 1, 1, 0,0,0,0,0,0, 1.0f);
}

// round 5
// speedup vs baseline: 6.7146x; 1.1977x over previous
#include <cuda_runtime.h>
#include <cuda_fp16.h>
#include <cstdint>
#include <math.h>

// ---------------- problem constants ----------------
#define B_   4
#define S_   1024
#define HD   2048
#define NH   16
#define NKV  4
#define DH   128
#define T_   (B_*S_)        // 4096
#define KVD  (NKV*DH)       // 512

// ---------------- scratch (device globals) ----------
__device__ float g_ao  [(size_t)T_*HD];
__device__ float g_gate[(size_t)T_*HD];
__device__ float g_up  [(size_t)T_*HD];
__device__ __half g_wqh[(size_t)HD*HD];
__device__ __half g_wkh[(size_t)HD*KVD];
__device__ __half g_wvh[(size_t)HD*KVD];
__device__ __half g_woh[(size_t)HD*HD];
__device__ __half g_wgh[(size_t)HD*HD];
__device__ __half g_wuh[(size_t)HD*HD];
__device__ __half g_wdh[(size_t)HD*HD];
__device__ __half g_xnh[(size_t)T_*HD];
__device__ __half g_qh [(size_t)T_*HD];
__device__ __half g_kh [(size_t)T_*KVD];
__device__ __half g_vh [(size_t)T_*KVD];
__device__ __half g_cxh[(size_t)T_*HD];
__device__ __half g_hh [(size_t)T_*HD];
__device__ __half g_guh[(size_t)T_*HD];

// ---------------- ptx helpers -----------------------
__device__ __forceinline__ void cpa16(unsigned int dst, const void* src) {
    asm volatile("cp.async.cg.shared.global [%0], [%1], 16;\n" :: "r"(dst), "l"(src));
}
__device__ __forceinline__ void cpa_commit() {
    asm volatile("cp.async.commit_group;\n");
}
template<int N>
__device__ __forceinline__ void cpa_wait() {
    asm volatile("cp.async.wait_group %0;\n" :: "n"(N));
}
__device__ __forceinline__ void ldsm4(unsigned &r0, unsigned &r1, unsigned &r2, unsigned &r3,
                                      unsigned int addr) {
    asm volatile("ldmatrix.sync.aligned.m8n8.x4.shared.b16 {%0,%1,%2,%3}, [%4];\n"
                 : "=r"(r0), "=r"(r1), "=r"(r2), "=r"(r3) : "r"(addr));
}
__device__ __forceinline__ void ldsm4t(unsigned &r0, unsigned &r1, unsigned &r2, unsigned &r3,
                                       unsigned int addr) {
    asm volatile("ldmatrix.sync.aligned.m8n8.x4.trans.shared.b16 {%0,%1,%2,%3}, [%4];\n"
                 : "=r"(r0), "=r"(r1), "=r"(r2), "=r"(r3) : "r"(addr));
}
__device__ __forceinline__ void mma16816(float c[4], const unsigned a[4], const unsigned b[2]) {
    asm volatile(
        "mma.sync.aligned.m16n8k16.row.col.f32.f16.f16.f32 "
        "{%0,%1,%2,%3},{%4,%5,%6,%7},{%8,%9},{%0,%1,%2,%3};\n"
        : "+f"(c[0]), "+f"(c[1]), "+f"(c[2]), "+f"(c[3])
        : "r"(a[0]), "r"(a[1]), "r"(a[2]), "r"(a[3]), "r"(b[0]), "r"(b[1]));
}
__device__ __forceinline__ unsigned packh2(float a, float b) {
    __half2 h = __floats2half2_rn(a, b);
    return *reinterpret_cast<unsigned*>(&h);
}

// ---------------- fp16 tensor-core GEMM (as R4) ----------------------------
template<bool NT, bool OUTH>
__global__ __launch_bounds__(256, 2)
void hgemm_k(const __half* __restrict__ A, const __half* __restrict__ B,
             float* __restrict__ Cf, __half* __restrict__ Ch,
             const float* __restrict__ bias, const float* __restrict__ resid,
             int M, int N, int K, int lda, int ldb, int ldc, int ldr,
             float scale) {
    constexpr int ASTG = 128 * 40;
    constexpr int BSTG = NT ? 128 * 40 : 32 * 136;
    extern __shared__ __half sm[];
    __half* sA = sm;
    __half* sB = sm + 3 * ASTG;

    const int tid = threadIdx.x, lane = tid & 31, warp = tid >> 5;
    const int warpM = warp >> 2, warpN = warp & 3;
    const int m0 = blockIdx.y * 128, n0 = blockIdx.x * 128;

    const unsigned suA = (unsigned)__cvta_generic_to_shared(sA);
    const unsigned suB = (unsigned)__cvta_generic_to_shared(sB);

    const int arow = tid >> 2, akc = tid & 3;
    const int bkr = tid >> 4, bnc = tid & 15;

    auto load_stage = [&](int kt, int buf) {
        const int k0 = kt << 5;
        #pragma unroll
        for (int i = 0; i < 2; i++) {
            int row = arow + i * 64;
            cpa16(suA + (unsigned)(buf * ASTG + row * 40 + akc * 8) * 2,
                  A + (long long)(m0 + row) * lda + k0 + akc * 8);
        }
        if (NT) {
            #pragma unroll
            for (int i = 0; i < 2; i++) {
                int row = arow + i * 64;
                cpa16(suB + (unsigned)(buf * BSTG + row * 40 + akc * 8) * 2,
                      B + (long long)(n0 + row) * ldb + k0 + akc * 8);
            }
        } else {
            #pragma unroll
            for (int i = 0; i < 2; i++) {
                int kr = bkr + i * 16;
                cpa16(suB + (unsigned)(buf * BSTG + kr * 136 + bnc * 8) * 2,
                      B + (long long)(k0 + kr) * ldb + n0 + bnc * 8);
            }
        }
    };

    float acc[4][4][4];
    #pragma unroll
    for (int i = 0; i < 4; i++)
        #pragma unroll
        for (int j = 0; j < 4; j++)
            #pragma unroll
            for (int q = 0; q < 4; q++) acc[i][j][q] = 0.f;

    const int ktiles = K >> 5;
    load_stage(0, 0); cpa_commit();
    if (ktiles > 1) load_stage(1, 1);
    cpa_commit();

    int buf = 0;
    for (int kt = 0; kt < ktiles; kt++) {
        cpa_wait<1>();
        __syncthreads();
        {
            int pf = kt + 2;
            if (pf < ktiles) {
                int pbuf = buf + 2; if (pbuf >= 3) pbuf -= 3;
                load_stage(pf, pbuf);
            }
            cpa_commit();
        }

        #pragma unroll
        for (int kk = 0; kk < 2; kk++) {
            unsigned af[4][4], bf[4][2];
            const int ar = warpM * 64 + (lane & 15);
            const int ac = kk * 16 + (lane >> 4) * 8;
            #pragma unroll
            for (int i = 0; i < 4; i++)
                ldsm4(af[i][0], af[i][1], af[i][2], af[i][3],
                      suA + (unsigned)(buf * ASTG + (ar + i * 16) * 40 + ac) * 2);

            if (NT) {
                const int br = (lane >> 4) * 8 + (lane & 7);
                const int bc = kk * 16 + ((lane >> 3) & 1) * 8;
                #pragma unroll
                for (int jj = 0; jj < 2; jj++) {
                    const int nb = warpN * 32 + jj * 16;
                    ldsm4(bf[jj*2][0], bf[jj*2][1], bf[jj*2+1][0], bf[jj*2+1][1],
                          suB + (unsigned)(buf * BSTG + (nb + br) * 40 + bc) * 2);
                }
            } else {
                const int kr = kk * 16 + (lane & 15);
                const int ncl = (lane >> 4) * 8;
                #pragma unroll
                for (int jj = 0; jj < 2; jj++) {
                    const int nb = warpN * 32 + jj * 16;
                    ldsm4t(bf[jj*2][0], bf[jj*2][1], bf[jj*2+1][0], bf[jj*2+1][1],
                           suB + (unsigned)(buf * BSTG + kr * 136 + nb + ncl) * 2);
                }
            }
            #pragma unroll
            for (int i = 0; i < 4; i++)
                #pragma unroll
                for (int j = 0; j < 4; j++)
                    mma16816(acc[i][j], af[i], bf[j]);
        }
        buf++; if (buf >= 3) buf -= 3;
    }

    #pragma unroll
    for (int i = 0; i < 4; i++) {
        const int r = m0 + warpM * 64 + i * 16 + (lane >> 2);
        #pragma unroll
        for (int j = 0; j < 4; j++) {
            const int cn = n0 + warpN * 32 + j * 8 + (lane & 3) * 2;
            float b0 = 0.f, b1 = 0.f;
            if (bias) { b0 = bias[cn]; b1 = bias[cn + 1]; }
            float v0 = acc[i][j][0] * scale + b0;
            float v1 = acc[i][j][1] * scale + b1;
            float v2 = acc[i][j][2] * scale + b0;
            float v3 = acc[i][j][3] * scale + b1;
            if (resid) {
                const float* rr0 = &resid[(long long)r * ldr + cn];
                const float* rr1 = &resid[(long long)(r + 8) * ldr + cn];
                v0 += rr0[0]; v1 += rr0[1]; v2 += rr1[0]; v3 += rr1[1];
            }
            if (OUTH) {
                *reinterpret_cast<__half2*>(&Ch[(long long)r * ldc + cn]) =
                    __floats2half2_rn(v0, v1);
                *reinterpret_cast<__half2*>(&Ch[(long long)(r + 8) * ldc + cn]) =
                    __floats2half2_rn(v2, v3);
            } else {
                *reinterpret_cast<float2*>(&Cf[(long long)r * ldc + cn]) = make_float2(v0, v1);
                *reinterpret_cast<float2*>(&Cf[(long long)(r + 8) * ldc + cn]) = make_float2(v2, v3);
            }
        }
    }
}

// ---------------- FlashAttention-2 (non-causal, GQA) ------------------------
// grid = (S/128, NH, B), 256 threads (8 warps), each warp owns 16 q-rows.
// KV tiles of 64, double-buffered cp.async. D = 128.
__global__ __launch_bounds__(256, 1)
void flash_k(const __half* __restrict__ Q, const __half* __restrict__ K,
             const __half* __restrict__ V, const float* __restrict__ mask,
             __half* __restrict__ O) {
    extern __shared__ char smraw[];
    float* smask = (float*)smraw;
    const unsigned suKV = (unsigned)__cvta_generic_to_shared(smraw + 4096);

    const int tid = threadIdx.x, lane = tid & 31, warp = tid >> 5;
    const int s0 = blockIdx.x * 128;
    const int h = blockIdx.y, b = blockIdx.z;
    const int kvh = h / (NH / NKV);

    const __half* Qg = Q + ((long long)(b * S_ + s0)) * HD + h * DH;
    const __half* Kg = K + ((long long)b * S_) * KVD + kvh * DH;
    const __half* Vg = V + ((long long)b * S_) * KVD + kvh * DH;

    // mask -> smem
    for (int i = tid; i < S_ / 4; i += 256)
        *(float4*)&smask[i * 4] = *(const float4*)&mask[b * S_ + i * 4];

    // stage Q (128x128) into KV smem area (reused afterwards)
    #pragma unroll
    for (int i = 0; i < 8; i++) {
        int idx = tid + 256 * i;
        int row = idx >> 4, col = (idx & 15) * 8;
        cpa16(suKV + (unsigned)(row * 136 + col) * 2, Qg + (long long)row * HD + col);
    }
    cpa_commit();
    cpa_wait<0>();
    __syncthreads();

    unsigned af[8][4];
    {
        const int ar = warp * 16 + (lane & 15);
        const int ac = (lane >> 4) * 8;
        #pragma unroll
        for (int t = 0; t < 8; t++)
            ldsm4(af[t][0], af[t][1], af[t][2], af[t][3],
                  suKV + (unsigned)(ar * 136 + t * 16 + ac) * 2);
    }
    __syncthreads();

    auto load_kv = [&](int tile, int stage) {
        const int kv0 = tile * 64;
        const unsigned kb = suKV + (unsigned)(stage * 17408) * 2;
        const unsigned vbx = kb + 8704u * 2;
        #pragma unroll
        for (int i = 0; i < 4; i++) {
            int idx = tid + 256 * i;
            int row = idx >> 4, col = (idx & 15) * 8;
            cpa16(kb + (unsigned)(row * 136 + col) * 2,
                  Kg + (long long)(kv0 + row) * KVD + col);
            cpa16(vbx + (unsigned)(row * 136 + col) * 2,
                  Vg + (long long)(kv0 + row) * KVD + col);
        }
    };

    load_kv(0, 0); cpa_commit();
    load_kv(1, 1); cpa_commit();

    float oacc[16][4];
    #pragma unroll
    for (int d = 0; d < 16; d++)
        #pragma unroll
        for (int q = 0; q < 4; q++) oacc[d][q] = 0.f;

    float m0r = -INFINITY, m1r = -INFINITY, l0r = 0.f, l1r = 0.f;
    const int r0 = warp * 16 + (lane >> 2);
    const float mq0 = smask[s0 + r0];
    const float mq1 = smask[s0 + r0 + 8];
    const float scale = 0.08838834764831845f;   // 1/sqrt(128)

    for (int t = 0; t < 16; t++) {
        cpa_wait<1>();
        __syncthreads();
        const int stage = t & 1;
        const unsigned kb = suKV + (unsigned)(stage * 17408) * 2;
        const unsigned vbx = kb + 8704u * 2;

        // S = Q @ K^T  (per warp 16x64)
        float sacc[8][4];
        #pragma unroll
        for (int j = 0; j < 8; j++)
            #pragma unroll
            for (int q = 0; q < 4; q++) sacc[j][q] = 0.f;

        #pragma unroll
        for (int ks = 0; ks < 8; ks++) {
            unsigned bf[8][2];
            #pragma unroll
            for (int g = 0; g < 4; g++) {
                const int br = g * 16 + (lane >> 4) * 8 + (lane & 7);
                const int bc = ks * 16 + ((lane >> 3) & 1) * 8;
                ldsm4(bf[g*2][0], bf[g*2][1], bf[g*2+1][0], bf[g*2+1][1],
                      kb + (unsigned)(br * 136 + bc) * 2);
            }
            #pragma unroll
            for (int j = 0; j < 8; j++)
                mma16816(sacc[j], af[ks], bf[j]);
        }

        // scale + mask + online softmax
        const int kvb = t * 64;
        float t0 = -INFINITY, t1 = -INFINITY;
        #pragma unroll
        for (int j = 0; j < 8; j++) {
            const int c = kvb + j * 8 + (lane & 3) * 2;
            const float mk0 = smask[c], mk1 = smask[c + 1];
            sacc[j][0] = (mq0 * mk0 == 0.f) ? -1e30f : sacc[j][0] * scale;
            sacc[j][1] = (mq0 * mk1 == 0.f) ? -1e30f : sacc[j][1] * scale;
            sacc[j][2] = (mq1 * mk0 == 0.f) ? -1e30f : sacc[j][2] * scale;
            sacc[j][3] = (mq1 * mk1 == 0.f) ? -1e30f : sacc[j][3] * scale;
            t0 = fmaxf(t0, fmaxf(sacc[j][0], sacc[j][1]));
            t1 = fmaxf(t1, fmaxf(sacc[j][2], sacc[j][3]));
        }
        t0 = fmaxf(t0, __shfl_xor_sync(0xffffffffu, t0, 1));
        t0 = fmaxf(t0, __shfl_xor_sync(0xffffffffu, t0, 2));
        t1 = fmaxf(t1, __shfl_xor_sync(0xffffffffu, t1, 1));
        t1 = fmaxf(t1, __shfl_xor_sync(0xffffffffu, t1, 2));

        const float mn0 = fmaxf(m0r, t0), mn1 = fmaxf(m1r, t1);
        const float a0 = __expf(m0r - mn0), a1 = __expf(m1r - mn1);
        m0r = mn0; m1r = mn1;

        float s0s = 0.f, s1s = 0.f;
        #pragma unroll
        for (int j = 0; j < 8; j++) {
            sacc[j][0] = __expf(sacc[j][0] - mn0);
            sacc[j][1] = __expf(sacc[j][1] - mn0);
            sacc[j][2] = __expf(sacc[j][2] - mn1);
            sacc[j][3] = __expf(sacc[j][3] - mn1);
            s0s += sacc[j][0] + sacc[j][1];
            s1s += sacc[j][2] + sacc[j][3];
        }
        s0s += __shfl_xor_sync(0xffffffffu, s0s, 1);
        s0s += __shfl_xor_sync(0xffffffffu, s0s, 2);
        s1s += __shfl_xor_sync(0xffffffffu, s1s, 1);
        s1s += __shfl_xor_sync(0xffffffffu, s1s, 2);
        l0r = l0r * a0 + s0s;
        l1r = l1r * a1 + s1s;

        #pragma unroll
        for (int d = 0; d < 16; d++) {
            oacc[d][0] *= a0; oacc[d][1] *= a0;
            oacc[d][2] *= a1; oacc[d][3] *= a1;
        }

        // pack P -> fp16 a-frags (4 k16-steps over 64 kv)
        unsigned pa[4][4];
        #pragma unroll
        for (int kk = 0; kk < 4; kk++) {
            pa[kk][0] = packh2(sacc[2*kk][0],   sacc[2*kk][1]);
            pa[kk][1] = packh2(sacc[2*kk][2],   sacc[2*kk][3]);
            pa[kk][2] = packh2(sacc[2*kk+1][0], sacc[2*kk+1][1]);
            pa[kk][3] = packh2(sacc[2*kk+1][2], sacc[2*kk+1][3]);
        }

        // O += P @ V
        #pragma unroll
        for (int kk = 0; kk < 4; kk++) {
            const int kr = kk * 16 + (lane & 15);
            const int ncl = (lane >> 4) * 8;
            unsigned vbf[16][2];
            #pragma unroll
            for (int dp = 0; dp < 8; dp++)
                ldsm4t(vbf[dp*2][0], vbf[dp*2][1], vbf[dp*2+1][0], vbf[dp*2+1][1],
                       vbx + (unsigned)(kr * 136 + dp * 16 + ncl) * 2);
            #pragma unroll
            for (int d = 0; d < 16; d++)
                mma16816(oacc[d], pa[kk], vbf[d]);
        }

        __syncthreads();
        if (t + 2 < 16) load_kv(t + 2, stage);
        cpa_commit();
    }

    // normalize + write ctx (fp16 packed [B,S,HD])
    const float i0 = 1.f / l0r, i1 = 1.f / l1r;
    __half* Og = O + ((long long)(b * S_ + s0 + r0)) * HD + h * DH;
    #pragma unroll
    for (int d = 0; d < 16; d++) {
        const int col = d * 8 + (lane & 3) * 2;
        *reinterpret_cast<__half2*>(&Og[col]) =
            __floats2half2_rn(oacc[d][0] * i0, oacc[d][1] * i0);
        *reinterpret_cast<__half2*>(&Og[(long long)8 * HD + col]) =
            __floats2half2_rn(oacc[d][2] * i1, oacc[d][3] * i1);
    }
}

// ---------------- elementwise kernels ---------------------------------------
__global__ void f2h_k(const float* __restrict__ a, __half* __restrict__ o, int n) {
    int i = (blockIdx.x * blockDim.x + threadIdx.x) * 8;
    if (i >= n) return;
    float4 v0 = *reinterpret_cast<const float4*>(&a[i]);
    float4 v1 = *reinterpret_cast<const float4*>(&a[i + 4]);
    uint4 u;
    u.x = packh2(v0.x, v0.y); u.y = packh2(v0.z, v0.w);
    u.z = packh2(v1.x, v1.y); u.w = packh2(v1.z, v1.w);
    *reinterpret_cast<uint4*>(&o[i]) = u;
}

__global__ void rmsnorm_h(const float* __restrict__ x, const float* __restrict__ g,
                          __half* __restrict__ o) {
    __shared__ float sh[256];
    int row = blockIdx.x;
    const float* xr = x + (long long)row * HD;
    float s = 0.f;
    for (int c = threadIdx.x; c < HD; c += 256) { float v = xr[c]; s += v * v; }
    sh[threadIdx.x] = s; __syncthreads();
    for (int st = 128; st > 0; st >>= 1) {
        if (threadIdx.x < st) sh[threadIdx.x] += sh[threadIdx.x + st];
        __syncthreads();
    }
    float inv = 1.0f / sqrtf(sh[0] / (float)HD + 1e-8f);
    __half* orow = o + (long long)row * HD;
    for (int c = threadIdx.x; c < HD; c += 256)
        orow[c] = __float2half(xr[c] * inv * g[c]);
}

__global__ void rope_h2(__half* __restrict__ x, int cols) {
    long long idx = (long long)blockIdx.x * blockDim.x + threadIdx.x;
    int halfc = cols >> 1;
    long long total = (long long)T_ * halfc;
    if (idx >= total) return;
    int pc = (int)(idx % halfc);
    int t  = (int)(idx / halfc);
    int s  = t % S_;
    int d  = (pc * 2) & (DH - 1);
    float inv = powf(10000.0f, -(float)d / (float)DH);
    float ang = (float)s * inv;
    float sn, cs; sincosf(ang, &sn, &cs);
    __half2* p = reinterpret_cast<__half2*>(x) + idx;
    float2 v = __half22float2(*p);
    *p = __floats2half2_rn(cs * v.x - sn * v.y, cs * v.y + sn * v.x);
}

__global__ void silu_k(const float* __restrict__ gate, const float* __restrict__ up,
                       __half* __restrict__ o) {
    long long i = (long long)blockIdx.x * blockDim.x + threadIdx.x;
    if (i >= (long long)T_ * HD) return;
    float gv = gate[i];
    float sg = 1.0f / (1.0f + expf(-gv));
    o[i] = __float2half(gv * sg * up[i]);
}

// ---------------- host side --------------------------------------------------
static const int SMEM_NT = 3 * (128 * 40 + 128 * 40) * 2;   // 61440
static const int SMEM_NN = 3 * (128 * 40 + 32 * 136) * 2;   // 56832
static const int SMEM_FA = 4096 + 2 * 2 * 8704 * 2;         // 73728

static void launch_hgemm(const __half* A, const __half* B,
                         float* Cf, __half* Ch,
                         const float* bias, const float* resid,
                         int M, int N, int K, int lda, int ldb, int ldc, int ldr,
                         float scale) {
    dim3 grid(N / 128, M / 128, 1), block(256);
    if (Ch) {
        cudaFuncSetAttribute(hgemm_k<false, true>,
                             cudaFuncAttributeMaxDynamicSharedMemorySize, SMEM_NN);
        hgemm_k<false, true><<<grid, block, SMEM_NN>>>(
            A, B, Cf, Ch, bias, resid, M, N, K, lda, ldb, ldc, ldr, scale);
    } else {
        cudaFuncSetAttribute(hgemm_k<false, false>,
                             cudaFuncAttributeMaxDynamicSharedMemorySize, SMEM_NN);
        hgemm_k<false, false><<<grid, block, SMEM_NN>>>(
            A, B, Cf, Ch, bias, resid, M, N, K, lda, ldb, ldc, ldr, scale);
    }
}

extern "C" void kernel_launch(void* const* d_in, const int* in_sizes, int n_in,
                              void* d_out, int out_size) {
    const float* enc    = (const float*)d_in[0];
    const float* mask   = (const float*)d_in[1];
    const float* gin    = (const float*)d_in[4];
    const float* gffn   = (const float*)d_in[5];
    const float* w_q    = (const float*)d_in[6];
    const float* b_q    = (const float*)d_in[7];
    const float* w_k    = (const float*)d_in[8];
    const float* b_k    = (const float*)d_in[9];
    const float* w_v    = (const float*)d_in[10];
    const float* b_v    = (const float*)d_in[11];
    const float* w_o    = (const float*)d_in[12];
    const float* b_o    = (const float*)d_in[13];
    const float* w_gate = (const float*)d_in[14];
    const float* b_gate = (const float*)d_in[15];
    const float* w_up   = (const float*)d_in[16];
    const float* b_up   = (const float*)d_in[17];
    const float* w_down = (const float*)d_in[18];
    const float* b_down = (const float*)d_in[19];
    float* out = (float*)d_out;

    float *ao, *gate, *up;
    __half *wqh, *wkh, *wvh, *woh, *wgh, *wuh, *wdh;
    __half *xnh, *qh, *kh, *vh, *cxh, *hh, *guh;
    cudaGetSymbolAddress((void**)&ao,  g_ao);
    cudaGetSymbolAddress((void**)&gate,g_gate);
    cudaGetSymbolAddress((void**)&up,  g_up);
    cudaGetSymbolAddress((void**)&wqh, g_wqh);
    cudaGetSymbolAddress((void**)&wkh, g_wkh);
    cudaGetSymbolAddress((void**)&wvh, g_wvh);
    cudaGetSymbolAddress((void**)&woh, g_woh);
    cudaGetSymbolAddress((void**)&wgh, g_wgh);
    cudaGetSymbolAddress((void**)&wuh, g_wuh);
    cudaGetSymbolAddress((void**)&wdh, g_wdh);
    cudaGetSymbolAddress((void**)&xnh, g_xnh);
    cudaGetSymbolAddress((void**)&qh,  g_qh);
    cudaGetSymbolAddress((void**)&kh,  g_kh);
    cudaGetSymbolAddress((void**)&vh,  g_vh);
    cudaGetSymbolAddress((void**)&cxh, g_cxh);
    cudaGetSymbolAddress((void**)&hh,  g_hh);
    cudaGetSymbolAddress((void**)&guh, g_guh);

    // 0) convert weights to fp16
    {
        int n1 = HD * HD, n2 = HD * KVD;
        f2h_k<<<n1 / 2048, 256>>>(w_q,    wqh, n1);
        f2h_k<<<n2 / 2048, 256>>>(w_k,    wkh, n2);
        f2h_k<<<n2 / 2048, 256>>>(w_v,    wvh, n2);
        f2h_k<<<n1 / 2048, 256>>>(w_o,    woh, n1);
        f2h_k<<<n1 / 2048, 256>>>(w_gate, wgh, n1);
        f2h_k<<<n1 / 2048, 256>>>(w_up,   wuh, n1);
        f2h_k<<<n1 / 2048, 256>>>(w_down, wdh, n1);
    }

    // 1) x = RMSNorm(enc) -> fp16
    rmsnorm_h<<<T_, 256>>>(enc, gin, xnh);

    // 2) Q/K/V projections -> fp16
    launch_hgemm(xnh, wqh, nullptr, qh, b_q, nullptr, T_, HD,  HD, HD, HD,  HD, 0, 1.0f);
    launch_hgemm(xnh, wkh, nullptr, kh, b_k, nullptr, T_, KVD, HD, HD, KVD, KVD, 0, 1.0f);
    launch_hgemm(xnh, wvh, nullptr, vh, b_v, nullptr, T_, KVD, HD, HD, KVD, KVD, 0, 1.0f);

    // 3) RoPE in place (fp16)
    {
        long long pq = (long long)T_ * HD / 2;
        long long pk = (long long)T_ * KVD / 2;
        rope_h2<<<(unsigned)((pq + 255) / 256), 256>>>(qh, HD);
        rope_h2<<<(unsigned)((pk + 255) / 256), 256>>>(kh, KVD);
    }

    // 4-6) fused flash attention -> ctx fp16 [B,S,HD]
    {
        cudaFuncSetAttribute(flash_k, cudaFuncAttributeMaxDynamicSharedMemorySize, SMEM_FA);
        dim3 grid(S_ / 128, NH, B_);
        flash_k<<<grid, 256, SMEM_FA>>>(qh, kh, vh, mask, cxh);
    }

    // 7) attn_out = enc + ctx @ w_o + b_o   (fp32)
    launch_hgemm(cxh, woh, ao, nullptr, b_o, enc, T_, HD, HD, HD, HD, HD, HD, 1.0f);

    // 8) h = RMSNorm(attn_out) -> fp16
    rmsnorm_h<<<T_, 256>>>(ao, gffn, hh);

    // 9) gate / up (fp32 outs)
    launch_hgemm(hh, wgh, gate, nullptr, b_gate, nullptr, T_, HD, HD, HD, HD, HD, 0, 1.0f);
    launch_hgemm(hh, wuh, up,   nullptr, b_up,   nullptr, T_, HD, HD, HD, HD, HD, 0, 1.0f);

    // 10) gu = SiLU(gate)*up -> fp16
    {
        long long n = (long long)T_ * HD;
        silu_k<<<(unsigned)((n + 255) / 256), 256>>>(gate, up, guh);
    }

    // 11) out = attn_out + gu @ w_down + b_down
    launch_hgemm(guh, wdh, out, nullptr, b_down, ao, T_, HD, HD, HD, HD, HD, HD, 1.0f);
}